// round 1
// baseline (speedup 1.0000x reference)
#include <cuda_runtime.h>

#define BATCH      8192
#define IN_F       4096
#define NCHUNK     8
#define CIN        512
#define COUT       512
#define TOPK       2

// Device-global scratch (no allocations allowed)
__device__ float g_act[NCHUNK];
__device__ int   g_idx[TOPK];

// ---------------------------------------------------------------------------
// 0) Zero the activity accumulators (graph replays need fresh state each call)
// ---------------------------------------------------------------------------
__global__ void init_kernel() {
    if (threadIdx.x < NCHUNK) g_act[threadIdx.x] = 0.0f;
}

// ---------------------------------------------------------------------------
// 1) Per-chunk sum of |x|. grid = (NCHUNK, BATCH/128), 256 threads.
//    Each block: 128 rows x 512 cols (one chunk slice) = 16384 float4 loads.
// ---------------------------------------------------------------------------
__global__ __launch_bounds__(256) void act_kernel(const float* __restrict__ x) {
    const int c       = blockIdx.x;
    const int rowbase = blockIdx.y * 128;
    const float* base = x + (size_t)rowbase * IN_F + c * CIN;

    float s = 0.0f;
#pragma unroll 4
    for (int it = 0; it < 64; ++it) {
        int lin = it * 256 + threadIdx.x;      // 0..16383
        int r   = lin >> 7;                     // /128 float4 per row
        int c4  = (lin & 127) << 2;             // float index within chunk
        float4 v = *(const float4*)(base + (size_t)r * IN_F + c4);
        s += fabsf(v.x) + fabsf(v.y) + fabsf(v.z) + fabsf(v.w);
    }
    // warp reduce
#pragma unroll
    for (int off = 16; off; off >>= 1) s += __shfl_xor_sync(0xffffffffu, s, off);
    __shared__ float ws[8];
    if ((threadIdx.x & 31) == 0) ws[threadIdx.x >> 5] = s;
    __syncthreads();
    if (threadIdx.x < 8) {
        s = ws[threadIdx.x];
#pragma unroll
        for (int off = 4; off; off >>= 1) s += __shfl_xor_sync(0xffu, s, off);
        if (threadIdx.x == 0) atomicAdd(&g_act[c], s);
    }
}

// ---------------------------------------------------------------------------
// 2) Finalize: mean, write activities to d_out tail, top-2 selection.
//    jax top_k: descending, ties -> lower index (strict > preserves this).
// ---------------------------------------------------------------------------
__global__ void finalize_kernel(float* __restrict__ out_act) {
    if (threadIdx.x == 0 && blockIdx.x == 0) {
        const float inv = 1.0f / ((float)BATCH * (float)CIN);
        float a[NCHUNK];
#pragma unroll
        for (int i = 0; i < NCHUNK; ++i) {
            a[i] = g_act[i] * inv;
            out_act[i] = a[i];
        }
        int i0 = 0;
#pragma unroll
        for (int i = 1; i < NCHUNK; ++i) if (a[i] > a[i0]) i0 = i;
        int i1 = (i0 == 0) ? 1 : 0;
#pragma unroll
        for (int i = 0; i < NCHUNK; ++i) if (i != i0 && a[i] > a[i1]) i1 = i;
        g_idx[0] = i0;
        g_idx[1] = i1;
    }
}

// ---------------------------------------------------------------------------
// 3) Zero the 6 non-selected chunks of the output (d_out is poisoned 0xAA).
//    Chunk is warp-uniform: 128 float4 per chunk, warps are 32-aligned.
// ---------------------------------------------------------------------------
__global__ __launch_bounds__(256) void zero_kernel(float4* __restrict__ out) {
    const int i0 = g_idx[0], i1 = g_idx[1];
    const size_t total  = (size_t)BATCH * IN_F / 4;
    const size_t stride = (size_t)gridDim.x * blockDim.x;
    for (size_t lin = (size_t)blockIdx.x * blockDim.x + threadIdx.x;
         lin < total; lin += stride) {
        int chunk = (int)((lin & 1023) >> 7);   // 1024 float4 per row, 128 per chunk
        if (chunk != i0 && chunk != i1)
            out[lin] = make_float4(0.f, 0.f, 0.f, 0.f);
    }
}

// ---------------------------------------------------------------------------
// 4) GEMM: out[b, chunk*512 + o] = sum_i x[b, chunk*512 + i] * W[chunk, o, i]
//          + bias[chunk, o]
//    Both operands K-major (NT). Tile 128x128x16, 256 thr, 8x8 per thread.
//    grid = (COUT/128, BATCH/128, TOPK)
// ---------------------------------------------------------------------------
__global__ __launch_bounds__(256) void gemm_kernel(
    const float* __restrict__ x, const float* __restrict__ W,
    const float* __restrict__ bias, float* __restrict__ out)
{
    const int BM = 128, BN = 128, BK = 16;
    const int chunk = g_idx[blockIdx.z];

    __shared__ float As[BK][BM];
    __shared__ float Bs[BK][BN];

    const int block_row = blockIdx.y;          // along batch
    const int block_col = blockIdx.x;          // along cout

    const float* xg = x + (size_t)(block_row * BM) * IN_F + chunk * CIN;
    const float* wg = W + (size_t)chunk * COUT * CIN + (size_t)(block_col * BN) * CIN;

    const int tid = threadIdx.x;
    const int tr  = tid >> 4;                  // 0..15 (rows of 8)
    const int tc  = tid & 15;                  // 0..15 (cols of 8)

    float acc[8][8];
#pragma unroll
    for (int i = 0; i < 8; ++i)
#pragma unroll
        for (int j = 0; j < 8; ++j) acc[i][j] = 0.0f;

    for (int k0 = 0; k0 < CIN; k0 += BK) {
        // Load 128x16 tiles of A and B: 512 float4 each, 2 per thread.
#pragma unroll
        for (int l = 0; l < 2; ++l) {
            int lin = l * 256 + tid;           // 0..511
            int row = lin >> 2;                // 0..127
            int k4  = (lin & 3) << 2;          // 0,4,8,12
            float4 va = *(const float4*)(xg + (size_t)row * IN_F + k0 + k4);
            As[k4 + 0][row] = va.x;
            As[k4 + 1][row] = va.y;
            As[k4 + 2][row] = va.z;
            As[k4 + 3][row] = va.w;
            float4 vb = *(const float4*)(wg + (size_t)row * CIN + k0 + k4);
            Bs[k4 + 0][row] = vb.x;
            Bs[k4 + 1][row] = vb.y;
            Bs[k4 + 2][row] = vb.z;
            Bs[k4 + 3][row] = vb.w;
        }
        __syncthreads();

#pragma unroll
        for (int kk = 0; kk < BK; ++kk) {
            float ra[8], rb[8];
#pragma unroll
            for (int i = 0; i < 8; ++i) ra[i] = As[kk][tr * 8 + i];
#pragma unroll
            for (int j = 0; j < 8; ++j) rb[j] = Bs[kk][tc * 8 + j];
#pragma unroll
            for (int i = 0; i < 8; ++i)
#pragma unroll
                for (int j = 0; j < 8; ++j) acc[i][j] += ra[i] * rb[j];
        }
        __syncthreads();
    }

    // Epilogue: add bias, scattered store into the chunk's output columns.
    const float* bg = bias + chunk * COUT + block_col * BN;
    float* og = out + (size_t)(block_row * BM) * IN_F + chunk * COUT + block_col * BN;

#pragma unroll
    for (int i = 0; i < 8; ++i) {
        int r = tr * 8 + i;
#pragma unroll
        for (int j = 0; j < 8; j += 4) {
            int c = tc * 8 + j;
            float4 v;
            v.x = acc[i][j + 0] + bg[c + 0];
            v.y = acc[i][j + 1] + bg[c + 1];
            v.z = acc[i][j + 2] + bg[c + 2];
            v.w = acc[i][j + 3] + bg[c + 3];
            *(float4*)(og + (size_t)r * IN_F + c) = v;
        }
    }
}

// ---------------------------------------------------------------------------
extern "C" void kernel_launch(void* const* d_in, const int* in_sizes, int n_in,
                              void* d_out, int out_size) {
    const float* x    = (const float*)d_in[0];
    const float* W    = (const float*)d_in[1];
    const float* bias = (const float*)d_in[2];
    float* out        = (float*)d_out;
    float* out_act    = out + (size_t)BATCH * IN_F;

    init_kernel<<<1, 32>>>();

    dim3 gact(NCHUNK, BATCH / 128);
    act_kernel<<<gact, 256>>>(x);

    finalize_kernel<<<1, 32>>>(out_act);

    zero_kernel<<<2048, 256>>>((float4*)out);

    dim3 ggemm(COUT / 128, BATCH / 128, TOPK);
    gemm_kernel<<<ggemm, 256>>>(x, W, bias, out);
}

// round 4
// speedup vs baseline: 1.8214x; 1.8214x over previous
#include <cuda_runtime.h>
#include <cuda_bf16.h>

#define BATCH      8192
#define IN_F       4096
#define NCHUNK     8
#define CIN        512
#define COUT       512
#define TOPK       2

// GEMM tiling (mma.sync path: no tcgen05 on this build target)
#define BM         128
#define BN         128
#define KC         32                   // fp32 K elems per chunk
#define NKCHUNK    (CIN / KC)           // 16
#define RS         40                   // padded row stride in bf16 elems (80 B)
#define RSB        (RS * 2)             // 80 bytes
#define AP         (BM * RSB)           // 10240 B per A plane
#define BP         (BN * RSB)           // 10240 B per B plane
#define STAGE      (2 * AP + 2 * BP)    // 40960 B
#define DSMEM_B    (2 * STAGE)          // 81920 B

// Device-global scratch
__device__ float g_act[NCHUNK];
__device__ int   g_idx[TOPK];

__device__ __forceinline__ unsigned smem_u32(const void* p) {
    unsigned a;
    asm("{ .reg .u64 t; cvta.to.shared.u64 t, %1; cvt.u32.u64 %0, t; }"
        : "=r"(a) : "l"(p));
    return a;
}

#define LDSM4(r0, r1, r2, r3, addr)                                        \
    asm volatile("ldmatrix.sync.aligned.m8n8.x4.shared.b16 {%0,%1,%2,%3}, [%4];" \
        : "=r"(r0), "=r"(r1), "=r"(r2), "=r"(r3) : "r"(addr))

#define MMA16816(c, a, b)                                                  \
    asm volatile("mma.sync.aligned.m16n8k16.row.col.f32.bf16.bf16.f32 "    \
        "{%0,%1,%2,%3}, {%4,%5,%6,%7}, {%8,%9}, {%0,%1,%2,%3};"            \
        : "+f"((c)[0]), "+f"((c)[1]), "+f"((c)[2]), "+f"((c)[3])           \
        : "r"((a)[0]), "r"((a)[1]), "r"((a)[2]), "r"((a)[3]),              \
          "r"((b)[0]), "r"((b)[1]))

// ---------------------------------------------------------------------------
// 0) init accumulators
// ---------------------------------------------------------------------------
__global__ void init_kernel() {
    if (threadIdx.x < NCHUNK) g_act[threadIdx.x] = 0.0f;
}

// ---------------------------------------------------------------------------
// 1) per-chunk |x| sum
// ---------------------------------------------------------------------------
__global__ __launch_bounds__(256) void act_kernel(const float* __restrict__ x) {
    const int c       = blockIdx.x;
    const int rowbase = blockIdx.y * 128;
    const float* base = x + (size_t)rowbase * IN_F + c * CIN;

    float s = 0.0f;
#pragma unroll 4
    for (int it = 0; it < 64; ++it) {
        int lin = it * 256 + threadIdx.x;
        int r   = lin >> 7;
        int c4  = (lin & 127) << 2;
        float4 v = *(const float4*)(base + (size_t)r * IN_F + c4);
        s += fabsf(v.x) + fabsf(v.y) + fabsf(v.z) + fabsf(v.w);
    }
#pragma unroll
    for (int off = 16; off; off >>= 1) s += __shfl_xor_sync(0xffffffffu, s, off);
    __shared__ float ws[8];
    if ((threadIdx.x & 31) == 0) ws[threadIdx.x >> 5] = s;
    __syncthreads();
    if (threadIdx.x < 8) {
        s = ws[threadIdx.x];
#pragma unroll
        for (int off = 4; off; off >>= 1) s += __shfl_xor_sync(0xffu, s, off);
        if (threadIdx.x == 0) atomicAdd(&g_act[c], s);
    }
}

// ---------------------------------------------------------------------------
// 2) finalize: mean + activities out + top-2 (strict >, lower index on ties)
// ---------------------------------------------------------------------------
__global__ void finalize_kernel(float* __restrict__ out_act) {
    if (threadIdx.x == 0 && blockIdx.x == 0) {
        const float inv = 1.0f / ((float)BATCH * (float)CIN);
        float a[NCHUNK];
#pragma unroll
        for (int i = 0; i < NCHUNK; ++i) {
            a[i] = g_act[i] * inv;
            out_act[i] = a[i];
        }
        int i0 = 0;
#pragma unroll
        for (int i = 1; i < NCHUNK; ++i) if (a[i] > a[i0]) i0 = i;
        int i1 = (i0 == 0) ? 1 : 0;
#pragma unroll
        for (int i = 0; i < NCHUNK; ++i) if (i != i0 && a[i] > a[i1]) i1 = i;
        g_idx[0] = i0;
        g_idx[1] = i1;
    }
}

// ---------------------------------------------------------------------------
// 3) zero non-selected chunks
// ---------------------------------------------------------------------------
__global__ __launch_bounds__(256) void zero_kernel(float4* __restrict__ out) {
    const int i0 = g_idx[0], i1 = g_idx[1];
    const size_t total  = (size_t)BATCH * IN_F / 4;
    const size_t stride = (size_t)gridDim.x * blockDim.x;
    for (size_t lin = (size_t)blockIdx.x * blockDim.x + threadIdx.x;
         lin < total; lin += stride) {
        int chunk = (int)((lin & 1023) >> 7);
        if (chunk != i0 && chunk != i1)
            out[lin] = make_float4(0.f, 0.f, 0.f, 0.f);
    }
}

// ---------------------------------------------------------------------------
// helper: split a float4 into packed bf16x2 hi (truncate) and lo (rn residual)
// ---------------------------------------------------------------------------
__device__ __forceinline__ void split4(float4 v, unsigned& hi01, unsigned& hi23,
                                       unsigned& lo01, unsigned& lo23) {
    unsigned u0 = __float_as_uint(v.x);
    unsigned u1 = __float_as_uint(v.y);
    unsigned u2 = __float_as_uint(v.z);
    unsigned u3 = __float_as_uint(v.w);
    hi01 = (u0 >> 16) | (u1 & 0xFFFF0000u);
    hi23 = (u2 >> 16) | (u3 & 0xFFFF0000u);
    float l0 = v.x - __uint_as_float(u0 & 0xFFFF0000u);
    float l1 = v.y - __uint_as_float(u1 & 0xFFFF0000u);
    float l2 = v.z - __uint_as_float(u2 & 0xFFFF0000u);
    float l3 = v.w - __uint_as_float(u3 & 0xFFFF0000u);
    __nv_bfloat162 p01 = __floats2bfloat162_rn(l0, l1);
    __nv_bfloat162 p23 = __floats2bfloat162_rn(l2, l3);
    lo01 = *(unsigned*)&p01;
    lo23 = *(unsigned*)&p23;
}

// ---------------------------------------------------------------------------
// 4) mma.sync GEMM, 3xBF16 split precision, double-buffered smem.
//    grid = (COUT/BN=4, BATCH/BM=64, TOPK=2), 256 threads (8 warps).
//    Warp tile 64m x 32n. Both operands K-major -> plain ldmatrix (no trans).
// ---------------------------------------------------------------------------
__global__ __launch_bounds__(256) void gemm_mma_kernel(
    const float* __restrict__ x, const float* __restrict__ W,
    const float* __restrict__ bias, float* __restrict__ out)
{
    extern __shared__ char dsm[];
    const unsigned smb = smem_u32(dsm);

    const int tid  = threadIdx.x;
    const int wid  = tid >> 5;
    const int lane = tid & 31;
    const int wm   = wid & 1;             // 2 m-warps (64 rows each)
    const int wn   = wid >> 1;            // 4 n-warps (32 cols each)

    const int nt    = blockIdx.x;         // 0..3
    const int mt    = blockIdx.y;         // 0..63
    const int chunk = g_idx[blockIdx.z];

    const float* xg = x + (size_t)(mt * BM) * IN_F + chunk * CIN;
    const float* wg = W + ((size_t)chunk * COUT + (size_t)nt * BN) * CIN;

    // gmem load mapping: lin = it*256 + tid, row = lin>>3, f4 = lin&7
    const int grow = tid >> 3;            // base row (advances by 32 per it)
    const int gf4  = tid & 7;

    // ldmatrix lane offsets (bytes within a plane)
    const unsigned a_lane = (unsigned)(((lane & 7) + ((lane >> 3) & 1) * 8) * RSB
                                       + ((lane >> 4) & 1) * 16);
    const unsigned b_lane = (unsigned)((((lane >> 4) & 1) * 8 + (lane & 7)) * RSB
                                       + ((lane >> 3) & 1) * 16);

    float acc[4][4][4];
#pragma unroll
    for (int i = 0; i < 4; ++i)
#pragma unroll
        for (int j = 0; j < 4; ++j)
#pragma unroll
            for (int k = 0; k < 4; ++k) acc[i][j][k] = 0.0f;

    float4 va[4], vb[4];

    // prologue: chunk 0 -> regs -> stage 0
#pragma unroll
    for (int it = 0; it < 4; ++it) {
        va[it] = *(const float4*)(xg + (size_t)(grow + it * 32) * IN_F + gf4 * 4);
        vb[it] = *(const float4*)(wg + (size_t)(grow + it * 32) * CIN + gf4 * 4);
    }
    {
        char* stg = dsm;
#pragma unroll
        for (int it = 0; it < 4; ++it) {
            int row = grow + it * 32;
            unsigned h01, h23, l01, l23;
            split4(va[it], h01, h23, l01, l23);
            *(uint2*)(stg + row * RSB + gf4 * 8)      = make_uint2(h01, h23);
            *(uint2*)(stg + AP + row * RSB + gf4 * 8) = make_uint2(l01, l23);
            split4(vb[it], h01, h23, l01, l23);
            *(uint2*)(stg + 2 * AP + row * RSB + gf4 * 8)      = make_uint2(h01, h23);
            *(uint2*)(stg + 2 * AP + BP + row * RSB + gf4 * 8) = make_uint2(l01, l23);
        }
    }
    __syncthreads();

    for (int c = 0; c < NKCHUNK; ++c) {
        const int s = c & 1;

        // prefetch next chunk into registers (overlaps with MMA below)
        if (c + 1 < NKCHUNK) {
            const int k0 = (c + 1) * KC;
#pragma unroll
            for (int it = 0; it < 4; ++it) {
                va[it] = *(const float4*)(xg + (size_t)(grow + it * 32) * IN_F + k0 + gf4 * 4);
                vb[it] = *(const float4*)(wg + (size_t)(grow + it * 32) * CIN + k0 + gf4 * 4);
            }
        }

        // ---- MMA over stage s ----
        const unsigned sa  = smb + s * STAGE + (unsigned)(wm * 64) * RSB;
        const unsigned sb_ = smb + s * STAGE + 2 * AP + (unsigned)(wn * 32) * RSB;

#pragma unroll
        for (int ks = 0; ks < 2; ++ks) {
            const unsigned ko = (unsigned)ks * 32;   // 16 bf16 = 32 B
            unsigned ah[4][4], bh[2][4], bl[2][4];
#pragma unroll
            for (int mb = 0; mb < 4; ++mb)
                LDSM4(ah[mb][0], ah[mb][1], ah[mb][2], ah[mb][3],
                      sa + (unsigned)(mb * 16) * RSB + ko + a_lane);
#pragma unroll
            for (int nb2 = 0; nb2 < 2; ++nb2) {
                LDSM4(bh[nb2][0], bh[nb2][1], bh[nb2][2], bh[nb2][3],
                      sb_ + (unsigned)(nb2 * 16) * RSB + ko + b_lane);
                LDSM4(bl[nb2][0], bl[nb2][1], bl[nb2][2], bl[nb2][3],
                      sb_ + BP + (unsigned)(nb2 * 16) * RSB + ko + b_lane);
            }
            // pass 1: Ahi * Bhi
#pragma unroll
            for (int mb = 0; mb < 4; ++mb)
#pragma unroll
                for (int nb = 0; nb < 4; ++nb)
                    MMA16816(acc[mb][nb], ah[mb], &bh[nb >> 1][(nb & 1) * 2]);
            // pass 2: Ahi * Blo
#pragma unroll
            for (int mb = 0; mb < 4; ++mb)
#pragma unroll
                for (int nb = 0; nb < 4; ++nb)
                    MMA16816(acc[mb][nb], ah[mb], &bl[nb >> 1][(nb & 1) * 2]);
            // load Alo over ah, pass 3: Alo * Bhi
#pragma unroll
            for (int mb = 0; mb < 4; ++mb)
                LDSM4(ah[mb][0], ah[mb][1], ah[mb][2], ah[mb][3],
                      sa + AP + (unsigned)(mb * 16) * RSB + ko + a_lane);
#pragma unroll
            for (int mb = 0; mb < 4; ++mb)
#pragma unroll
                for (int nb = 0; nb < 4; ++nb)
                    MMA16816(acc[mb][nb], ah[mb], &bh[nb >> 1][(nb & 1) * 2]);
        }

        // ---- store next chunk into the other stage ----
        if (c + 1 < NKCHUNK) {
            char* stg = dsm + (s ^ 1) * STAGE;
#pragma unroll
            for (int it = 0; it < 4; ++it) {
                int row = grow + it * 32;
                unsigned h01, h23, l01, l23;
                split4(va[it], h01, h23, l01, l23);
                *(uint2*)(stg + row * RSB + gf4 * 8)      = make_uint2(h01, h23);
                *(uint2*)(stg + AP + row * RSB + gf4 * 8) = make_uint2(l01, l23);
                split4(vb[it], h01, h23, l01, l23);
                *(uint2*)(stg + 2 * AP + row * RSB + gf4 * 8)      = make_uint2(h01, h23);
                *(uint2*)(stg + 2 * AP + BP + row * RSB + gf4 * 8) = make_uint2(l01, l23);
            }
        }
        __syncthreads();
    }

    // ---- epilogue: bias + scattered store ----
    const int g   = lane >> 2;
    const int tig = lane & 3;
    const float* bg = bias + chunk * COUT + nt * BN + wn * 32;
    float* og = out + (size_t)(mt * BM + wm * 64) * IN_F + chunk * COUT + nt * BN + wn * 32;

#pragma unroll
    for (int mb = 0; mb < 4; ++mb) {
#pragma unroll
        for (int nb = 0; nb < 4; ++nb) {
            int col = nb * 8 + tig * 2;
            float b0 = bg[col], b1 = bg[col + 1];
            int r0 = mb * 16 + g;
            float2 v0 = make_float2(acc[mb][nb][0] + b0, acc[mb][nb][1] + b1);
            float2 v1 = make_float2(acc[mb][nb][2] + b0, acc[mb][nb][3] + b1);
            *(float2*)(og + (size_t)r0 * IN_F + col)       = v0;
            *(float2*)(og + (size_t)(r0 + 8) * IN_F + col) = v1;
        }
    }
}

// ---------------------------------------------------------------------------
extern "C" void kernel_launch(void* const* d_in, const int* in_sizes, int n_in,
                              void* d_out, int out_size) {
    const float* x    = (const float*)d_in[0];
    const float* W    = (const float*)d_in[1];
    const float* bias = (const float*)d_in[2];
    float* out        = (float*)d_out;
    float* out_act    = out + (size_t)BATCH * IN_F;

    cudaFuncSetAttribute(gemm_mma_kernel,
                         cudaFuncAttributeMaxDynamicSharedMemorySize, DSMEM_B);

    init_kernel<<<1, 32>>>();

    dim3 gact(NCHUNK, BATCH / 128);
    act_kernel<<<gact, 256>>>(x);

    finalize_kernel<<<1, 32>>>(out_act);

    zero_kernel<<<2048, 256>>>((float4*)out);

    dim3 ggemm(COUT / BN, BATCH / BM, TOPK);
    gemm_mma_kernel<<<ggemm, 256, DSMEM_B>>>(x, W, bias, out);
}

// round 7
// speedup vs baseline: 2.2406x; 1.2301x over previous
#include <cuda_runtime.h>
#include <cuda_bf16.h>

#define BATCH      8192
#define IN_F       4096
#define NCHUNK     8
#define CIN        512
#define COUT       512
#define TOPK       2

// GEMM tiling (mma.sync path)
#define BM         128
#define BN         128
#define KC         32                   // fp32 K elems per chunk
#define NKCHUNK    (CIN / KC)           // 16
#define RS         40                   // padded bf16 row stride (80 B)
#define RSB        (RS * 2)
#define AP         (BM * RSB)           // 10240 B per bf16 plane
#define BP         (BN * RSB)
#define STAGE      (2 * AP + 2 * BP)    // 40960 B (Ahi,Alo,Bhi,Blo)
// fp32 staging: rows of 32 floats, 128 B pitch (16B-aligned for cp.async/LDS.128;
// each 8-lane phase reads one row -> all 32 banks -> conflict-free unpadded)
#define FROW       128
#define FPA        (BM * FROW)          // 16384 B
#define FP32_OFF   STAGE
#define DSMEM_B    (STAGE + 2 * FPA)    // 73728 B

// Device-global scratch (zero-initialized at module load; restored each run)
__device__ float    g_act[NCHUNK];
__device__ unsigned g_tick;
__device__ int      g_idx[TOPK];

__device__ __forceinline__ unsigned smem_u32(const void* p) {
    unsigned a;
    asm("{ .reg .u64 t; cvta.to.shared.u64 t, %1; cvt.u32.u64 %0, t; }"
        : "=r"(a) : "l"(p));
    return a;
}

#define LDSM4(r0, r1, r2, r3, addr)                                        \
    asm volatile("ldmatrix.sync.aligned.m8n8.x4.shared.b16 {%0,%1,%2,%3}, [%4];" \
        : "=r"(r0), "=r"(r1), "=r"(r2), "=r"(r3) : "r"(addr))

#define MMA16816(c, a, b)                                                  \
    asm volatile("mma.sync.aligned.m16n8k16.row.col.f32.bf16.bf16.f32 "    \
        "{%0,%1,%2,%3}, {%4,%5,%6,%7}, {%8,%9}, {%0,%1,%2,%3};"            \
        : "+f"((c)[0]), "+f"((c)[1]), "+f"((c)[2]), "+f"((c)[3])           \
        : "r"((a)[0]), "r"((a)[1]), "r"((a)[2]), "r"((a)[3]),              \
          "r"((b)[0]), "r"((b)[1]))

#define CP16(dst, src)                                                     \
    asm volatile("cp.async.cg.shared.global [%0], [%1], 16;"               \
        :: "r"(dst), "l"(src))
#define CP_COMMIT() asm volatile("cp.async.commit_group;" ::: "memory")
#define CP_WAIT0()  asm volatile("cp.async.wait_group 0;" ::: "memory")

// ---------------------------------------------------------------------------
// 1) act + finalize (ticket): per-chunk mean|x|, top-2, write activities.
//    grid = (NCHUNK, 64), 256 threads. Last block finalizes and resets state.
// ---------------------------------------------------------------------------
__global__ __launch_bounds__(256) void act_fused_kernel(
    const float* __restrict__ x, float* __restrict__ out_act)
{
    const int c       = blockIdx.x;
    const int rowbase = blockIdx.y * 128;
    const float* base = x + (size_t)rowbase * IN_F + c * CIN;

    float s = 0.0f;
#pragma unroll 4
    for (int it = 0; it < 64; ++it) {
        int lin = it * 256 + threadIdx.x;
        int r   = lin >> 7;
        int c4  = (lin & 127) << 2;
        float4 v = *(const float4*)(base + (size_t)r * IN_F + c4);
        s += fabsf(v.x) + fabsf(v.y) + fabsf(v.z) + fabsf(v.w);
    }
#pragma unroll
    for (int off = 16; off; off >>= 1) s += __shfl_xor_sync(0xffffffffu, s, off);
    __shared__ float ws[8];
    if ((threadIdx.x & 31) == 0) ws[threadIdx.x >> 5] = s;
    __syncthreads();
    if (threadIdx.x == 0) {
        s = ws[0];
#pragma unroll
        for (int i = 1; i < 8; ++i) s += ws[i];
        atomicAdd(&g_act[c], s);
        __threadfence();
        unsigned t = atomicAdd(&g_tick, 1u);
        if (t == (unsigned)(NCHUNK * 64 - 1)) {
            // finalize
            const float inv = 1.0f / ((float)BATCH * (float)CIN);
            float a[NCHUNK];
#pragma unroll
            for (int i = 0; i < NCHUNK; ++i) {
                a[i] = g_act[i] * inv;
                out_act[i] = a[i];
            }
            int i0 = 0;
#pragma unroll
            for (int i = 1; i < NCHUNK; ++i) if (a[i] > a[i0]) i0 = i;
            int i1 = (i0 == 0) ? 1 : 0;
#pragma unroll
            for (int i = 0; i < NCHUNK; ++i) if (i != i0 && a[i] > a[i1]) i1 = i;
            g_idx[0] = i0;
            g_idx[1] = i1;
            // reset for next graph replay
#pragma unroll
            for (int i = 0; i < NCHUNK; ++i) g_act[i] = 0.0f;
            g_tick = 0u;
            __threadfence();
        }
    }
}

// ---------------------------------------------------------------------------
// split a float4 into packed bf16x2 hi (truncate) and lo (rn residual)
// ---------------------------------------------------------------------------
__device__ __forceinline__ void split4(float4 v, unsigned& hi01, unsigned& hi23,
                                       unsigned& lo01, unsigned& lo23) {
    unsigned u0 = __float_as_uint(v.x);
    unsigned u1 = __float_as_uint(v.y);
    unsigned u2 = __float_as_uint(v.z);
    unsigned u3 = __float_as_uint(v.w);
    hi01 = (u0 >> 16) | (u1 & 0xFFFF0000u);
    hi23 = (u2 >> 16) | (u3 & 0xFFFF0000u);
    float l0 = v.x - __uint_as_float(u0 & 0xFFFF0000u);
    float l1 = v.y - __uint_as_float(u1 & 0xFFFF0000u);
    float l2 = v.z - __uint_as_float(u2 & 0xFFFF0000u);
    float l3 = v.w - __uint_as_float(u3 & 0xFFFF0000u);
    __nv_bfloat162 p01 = __floats2bfloat162_rn(l0, l1);
    __nv_bfloat162 p23 = __floats2bfloat162_rn(l2, l3);
    lo01 = *(unsigned*)&p01;
    lo23 = *(unsigned*)&p23;
}

// ---------------------------------------------------------------------------
// 2) GEMM (3xBF16 split, mma.sync) + folded zeroing of non-selected chunks.
//    grid = (4, 64, 2), 256 threads, occupancy 2.
//    cp.async stages fp32 -> smem; producer LDS->split->STS single bf16 stage.
// ---------------------------------------------------------------------------
__global__ __launch_bounds__(256, 2) void gemm_mma_kernel(
    const float* __restrict__ x, const float* __restrict__ W,
    const float* __restrict__ bias, float* __restrict__ out)
{
    extern __shared__ char dsm[];
    const unsigned smb = smem_u32(dsm);

    const int tid  = threadIdx.x;
    const int lane = tid & 31;
    const int wid  = tid >> 5;
    const int wm   = wid & 1;             // 2 m-warps (64 rows)
    const int wn   = wid >> 1;            // 4 n-warps (32 cols)

    const int nt    = blockIdx.x;         // 0..3
    const int mt    = blockIdx.y;         // 0..63
    const int zz    = blockIdx.z;         // 0..1
    const int chunk = g_idx[zz];
    const int zslot = nt + 4 * zz;        // 0..7 -> 64-col slice for zeroing

    // 6 non-selected chunks (for zero-fold)
    int nz[6];
    {
        int s0 = g_idx[0], s1 = g_idx[1], k = 0;
#pragma unroll
        for (int i = 0; i < NCHUNK; ++i)
            if (i != s0 && i != s1) nz[k++] = i;
    }

    const float* xg = x + (size_t)(mt * BM) * IN_F + chunk * CIN;
    const float* wg = W + ((size_t)chunk * COUT + (size_t)nt * BN) * CIN;

    // cp.async mapping: thread handles rows (tid>>3)+32*it, f4 = tid&7
    const int grow = tid >> 3;
    const int gf4  = tid & 7;

    // ldmatrix lane offsets (bytes within a bf16 plane)
    const unsigned a_lane = (unsigned)(((lane & 7) + ((lane >> 3) & 1) * 8) * RSB
                                       + ((lane >> 4) & 1) * 16);
    const unsigned b_lane = (unsigned)((((lane >> 4) & 1) * 8 + (lane & 7)) * RSB
                                       + ((lane >> 3) & 1) * 16);

    const unsigned fA = smb + FP32_OFF;
    const unsigned fB = fA + FPA;

    float acc[4][4][4];
#pragma unroll
    for (int i = 0; i < 4; ++i)
#pragma unroll
        for (int j = 0; j < 4; ++j)
#pragma unroll
            for (int k = 0; k < 4; ++k) acc[i][j][k] = 0.0f;

    // ---- producer: fp32 stage -> split -> bf16 planes ----
    auto produce = [&]() {
#pragma unroll
        for (int it = 0; it < 4; ++it) {
            int row = grow + it * 32;
            float4 va = *(const float4*)(dsm + FP32_OFF + row * FROW + gf4 * 16);
            float4 vb = *(const float4*)(dsm + FP32_OFF + FPA + row * FROW + gf4 * 16);
            unsigned h01, h23, l01, l23;
            split4(va, h01, h23, l01, l23);
            *(uint2*)(dsm + row * RSB + gf4 * 8)      = make_uint2(h01, h23);
            *(uint2*)(dsm + AP + row * RSB + gf4 * 8) = make_uint2(l01, l23);
            split4(vb, h01, h23, l01, l23);
            *(uint2*)(dsm + 2 * AP + row * RSB + gf4 * 8)      = make_uint2(h01, h23);
            *(uint2*)(dsm + 2 * AP + BP + row * RSB + gf4 * 8) = make_uint2(l01, l23);
        }
    };
    auto cp_chunk = [&](int c) {
        const int k0 = c * KC;
#pragma unroll
        for (int it = 0; it < 4; ++it) {
            int row = grow + it * 32;
            CP16(fA + row * FROW + gf4 * 16, xg + (size_t)row * IN_F + k0 + gf4 * 4);
            CP16(fB + row * FROW + gf4 * 16, wg + (size_t)row * CIN + k0 + gf4 * 4);
        }
        CP_COMMIT();
    };

    // prologue: chunk 0
    cp_chunk(0);
    CP_WAIT0();
    produce();
    __syncthreads();

    for (int c = 0; c < NKCHUNK; ++c) {
        if (c + 1 < NKCHUNK) cp_chunk(c + 1);

        // folded zeroing: 3 float4 stores per thread per iter (disjoint region)
        {
#pragma unroll
            for (int j = 0; j < 3; ++j) {
                int e   = (c * 3 + j) * 256 + tid;       // 0..12287
                int f4c = e & 15;
                int row = (e >> 4) & 127;
                int c6  = e >> 11;                       // 0..5
                float4* dst = (float4*)out
                    + (size_t)(mt * 128 + row) * (IN_F / 4)
                    + nz[c6] * (COUT / 4) + zslot * 16 + f4c;
                *dst = make_float4(0.f, 0.f, 0.f, 0.f);
            }
        }

        // ---- MMA over stage (chunk c) ----
        const unsigned sa  = smb + (unsigned)(wm * 64) * RSB;
        const unsigned sb_ = smb + 2 * AP + (unsigned)(wn * 32) * RSB;
#pragma unroll
        for (int ks = 0; ks < 2; ++ks) {
            const unsigned ko = (unsigned)ks * 32;       // 16 bf16 = 32 B
            unsigned ah[4][4], bh[2][4], bl[2][4];
#pragma unroll
            for (int mb = 0; mb < 4; ++mb)
                LDSM4(ah[mb][0], ah[mb][1], ah[mb][2], ah[mb][3],
                      sa + (unsigned)(mb * 16) * RSB + ko + a_lane);
#pragma unroll
            for (int nb2 = 0; nb2 < 2; ++nb2) {
                LDSM4(bh[nb2][0], bh[nb2][1], bh[nb2][2], bh[nb2][3],
                      sb_ + (unsigned)(nb2 * 16) * RSB + ko + b_lane);
                LDSM4(bl[nb2][0], bl[nb2][1], bl[nb2][2], bl[nb2][3],
                      sb_ + BP + (unsigned)(nb2 * 16) * RSB + ko + b_lane);
            }
#pragma unroll
            for (int mb = 0; mb < 4; ++mb)
#pragma unroll
                for (int nb = 0; nb < 4; ++nb)
                    MMA16816(acc[mb][nb], ah[mb], &bh[nb >> 1][(nb & 1) * 2]);
#pragma unroll
            for (int mb = 0; mb < 4; ++mb)
#pragma unroll
                for (int nb = 0; nb < 4; ++nb)
                    MMA16816(acc[mb][nb], ah[mb], &bl[nb >> 1][(nb & 1) * 2]);
#pragma unroll
            for (int mb = 0; mb < 4; ++mb)
                LDSM4(ah[mb][0], ah[mb][1], ah[mb][2], ah[mb][3],
                      sa + AP + (unsigned)(mb * 16) * RSB + ko + a_lane);
#pragma unroll
            for (int mb = 0; mb < 4; ++mb)
#pragma unroll
                for (int nb = 0; nb < 4; ++nb)
                    MMA16816(acc[mb][nb], ah[mb], &bh[nb >> 1][(nb & 1) * 2]);
        }
        __syncthreads();                 // stage fully read by all warps

        if (c + 1 < NKCHUNK) {
            CP_WAIT0();
            produce();                   // overwrite stage with chunk c+1
        }
        __syncthreads();
    }

    // ---- epilogue: bias + scattered store ----
    const int g   = lane >> 2;
    const int tig = lane & 3;
    const float* bg = bias + chunk * COUT + nt * BN + wn * 32;
    float* og = out + (size_t)(mt * BM + wm * 64) * IN_F + chunk * COUT + nt * BN + wn * 32;

#pragma unroll
    for (int mb = 0; mb < 4; ++mb) {
#pragma unroll
        for (int nb = 0; nb < 4; ++nb) {
            int col = nb * 8 + tig * 2;
            float b0 = bg[col], b1 = bg[col + 1];
            int r0 = mb * 16 + g;
            float2 v0 = make_float2(acc[mb][nb][0] + b0, acc[mb][nb][1] + b1);
            float2 v1 = make_float2(acc[mb][nb][2] + b0, acc[mb][nb][3] + b1);
            *(float2*)(og + (size_t)r0 * IN_F + col)       = v0;
            *(float2*)(og + (size_t)(r0 + 8) * IN_F + col) = v1;
        }
    }
}

// ---------------------------------------------------------------------------
extern "C" void kernel_launch(void* const* d_in, const int* in_sizes, int n_in,
                              void* d_out, int out_size) {
    const float* x    = (const float*)d_in[0];
    const float* W    = (const float*)d_in[1];
    const float* bias = (const float*)d_in[2];
    float* out        = (float*)d_out;
    float* out_act    = out + (size_t)BATCH * IN_F;

    cudaFuncSetAttribute(gemm_mma_kernel,
                         cudaFuncAttributeMaxDynamicSharedMemorySize, DSMEM_B);

    dim3 gact(NCHUNK, BATCH / 128);
    act_fused_kernel<<<gact, 256>>>(x, out_act);

    dim3 ggemm(COUT / BN, BATCH / BM, TOPK);
    gemm_mma_kernel<<<ggemm, 256, DSMEM_B>>>(x, W, bias, out);
}